// round 8
// baseline (speedup 1.0000x reference)
#include <cuda_runtime.h>
#include <cuda_fp16.h>

#define N_CAP 100000
#define E_CAP 1600000
#define F_DIM 128

// -------- static scratch (allocation-free rule) --------
__device__ uint2 g_xh [(size_t)N_CAP * 32];   // x  rows in fp16 (25.6 MB)
__device__ uint2 g_h1h[(size_t)N_CAP * 32];   // h1 rows in fp16 (25.6 MB)
__device__ float g_dinv[N_CAP];
__device__ int   g_rowptr[N_CAP + 1];
__device__ int   g_cnt[N_CAP];                // histogram -> cursor
__device__ int2  g_cw[E_CAP];                 // (src, bitcast(dinv[src])) sorted by dst
__device__ int   g_bsums[1024];
__device__ int   g_is64;

// -------- 1) prep: zero histogram + parallel dtype detect + x -> fp16 --------
__global__ void prep_k(const float2* __restrict__ x, const void* ei, int N, int NF2) {
    if (blockIdx.x == 0 && threadIdx.x < 32) {
        const long long* el = (const long long*)ei;
        int ok = 1;
        #pragma unroll
        for (int i = threadIdx.x; i < 128; i += 32) {
            long long v = el[i];
            if (v < 0 || v >= (1LL << 31)) ok = 0;
        }
        ok = __all_sync(0xffffffffu, ok);
        if (threadIdx.x == 0) g_is64 = ok;
    }
    int idx    = blockIdx.x * blockDim.x + threadIdx.x;
    int stride = gridDim.x * blockDim.x;
    for (int i = idx; i < N; i += stride) g_cnt[i] = 0;
    for (int i = idx; i < NF2; i += stride) {
        float2 v = x[i];
        ((__half2*)g_xh)[i] = __floats2half2_rn(v.x, v.y);
    }
}

// -------- 2) histogram of dst --------
__global__ void hist_k(const void* ei, int E) {
    int e = blockIdx.x * blockDim.x + threadIdx.x;
    if (e >= E) return;
    int dst;
    if (g_is64) dst = (int)((const long long*)ei)[(size_t)E + e];
    else        dst = ((const int*)ei)[(size_t)E + e];
    atomicAdd(&g_cnt[dst], 1);
}

// -------- 3) per-1024-chunk totals --------
__global__ void scan1_k(int N) {
    __shared__ int sh[256];
    int base = blockIdx.x * 1024;
    int tid  = threadIdx.x;
    int s = 0;
    #pragma unroll
    for (int k = 0; k < 4; k++) {
        int i = base + tid + k * 256;
        if (i < N) s += g_cnt[i];
    }
    sh[tid] = s; __syncthreads();
    for (int off = 128; off > 0; off >>= 1) {
        if (tid < off) sh[tid] += sh[tid + off];
        __syncthreads();
    }
    if (tid == 0) g_bsums[blockIdx.x] = sh[0];
}

// -------- 4) fused: block prefix + local scan + rowptr + cursor + dinv --------
__global__ void scan3_k(int N) {
    __shared__ int sh[1024];
    __shared__ int bpref;
    int tid = threadIdx.x, bid = blockIdx.x;
    if (tid < 32) {
        int s = 0;
        for (int b = tid; b < bid; b += 32) s += g_bsums[b];
        #pragma unroll
        for (int o = 16; o > 0; o >>= 1) s += __shfl_xor_sync(0xffffffffu, s, o);
        if (tid == 0) bpref = s;
    }
    int i   = bid * 1024 + tid;
    int own = (i < N) ? g_cnt[i] : 0;
    sh[tid] = own; __syncthreads();
    for (int off = 1; off < 1024; off <<= 1) {
        int v = (tid >= off) ? sh[tid - off] : 0;
        __syncthreads();
        sh[tid] += v;
        __syncthreads();
    }
    if (i < N) {
        int excl = bpref + sh[tid] - own;
        g_rowptr[i] = excl;
        g_cnt[i]    = excl;                       // scatter cursor
        g_dinv[i]   = rsqrtf((float)own + 1.0f);
        if (i == N - 1) g_rowptr[N] = excl + own;
    }
}

// -------- 5) scatter edges into CSR with precomputed source weight --------
__global__ void scatter_k(const void* ei, int E) {
    int e = blockIdx.x * blockDim.x + threadIdx.x;
    if (e >= E) return;
    int src, dst;
    if (g_is64) {
        src = (int)((const long long*)ei)[e];
        dst = (int)((const long long*)ei)[(size_t)E + e];
    } else {
        src = ((const int*)ei)[e];
        dst = ((const int*)ei)[(size_t)E + e];
    }
    int pos = atomicAdd(&g_cnt[dst], 1);
    g_cw[pos] = make_int2(src, __float_as_int(g_dinv[src]));
}

// -------- gather-accumulate core: fp16 rows, fp32 accum, MLP=4 + prefetch --------
__device__ __forceinline__ void edge_fma(float4& acc, const uint2* __restrict__ tab,
                                         int lane, int2 cw, int k) {
    int   s = __shfl_sync(0xffffffffu, cw.x, k);
    float w = __int_as_float(__shfl_sync(0xffffffffu, cw.y, k));
    uint2 u = tab[(size_t)s * 32 + lane];
    float2 a = __half22float2(*(const __half2*)&u.x);
    float2 b = __half22float2(*(const __half2*)&u.y);
    acc.x = fmaf(w, a.x, acc.x);
    acc.y = fmaf(w, a.y, acc.y);
    acc.z = fmaf(w, b.x, acc.z);
    acc.w = fmaf(w, b.y, acc.w);
}

__device__ __forceinline__ float4 hop_row(const uint2* __restrict__ tab,
                                          int gw, int lane) {
    int beg = g_rowptr[gw], end = g_rowptr[gw + 1];
    float4 acc = make_float4(0.f, 0.f, 0.f, 0.f);

    int2 cw = make_int2(0, 0);
    if (beg + lane < end) cw = g_cw[beg + lane];

    for (int j = beg; j < end; j += 32) {
        // prefetch next chunk's edge data (overlaps with the 8 inner iterations)
        int2 cw_next = make_int2(0, 0);
        if (j + 32 + lane < end) cw_next = g_cw[j + 32 + lane];

        int cnt = min(32, end - j);
        int k = 0;
        for (; k + 3 < cnt; k += 4) {
            int   s0 = __shfl_sync(0xffffffffu, cw.x, k);
            float w0 = __int_as_float(__shfl_sync(0xffffffffu, cw.y, k));
            int   s1 = __shfl_sync(0xffffffffu, cw.x, k + 1);
            float w1 = __int_as_float(__shfl_sync(0xffffffffu, cw.y, k + 1));
            int   s2 = __shfl_sync(0xffffffffu, cw.x, k + 2);
            float w2 = __int_as_float(__shfl_sync(0xffffffffu, cw.y, k + 2));
            int   s3 = __shfl_sync(0xffffffffu, cw.x, k + 3);
            float w3 = __int_as_float(__shfl_sync(0xffffffffu, cw.y, k + 3));
            // 4 independent gathers in flight
            uint2 u0 = tab[(size_t)s0 * 32 + lane];
            uint2 u1 = tab[(size_t)s1 * 32 + lane];
            uint2 u2 = tab[(size_t)s2 * 32 + lane];
            uint2 u3 = tab[(size_t)s3 * 32 + lane];
            float2 a0 = __half22float2(*(const __half2*)&u0.x);
            float2 b0 = __half22float2(*(const __half2*)&u0.y);
            float2 a1 = __half22float2(*(const __half2*)&u1.x);
            float2 b1 = __half22float2(*(const __half2*)&u1.y);
            float2 a2 = __half22float2(*(const __half2*)&u2.x);
            float2 b2 = __half22float2(*(const __half2*)&u2.y);
            float2 a3 = __half22float2(*(const __half2*)&u3.x);
            float2 b3 = __half22float2(*(const __half2*)&u3.y);
            acc.x = fmaf(w0, a0.x, fmaf(w1, a1.x, fmaf(w2, a2.x, fmaf(w3, a3.x, acc.x))));
            acc.y = fmaf(w0, a0.y, fmaf(w1, a1.y, fmaf(w2, a2.y, fmaf(w3, a3.y, acc.y))));
            acc.z = fmaf(w0, b0.x, fmaf(w1, b1.x, fmaf(w2, b2.x, fmaf(w3, b3.x, acc.z))));
            acc.w = fmaf(w0, b0.y, fmaf(w1, b1.y, fmaf(w2, b2.y, fmaf(w3, b3.y, acc.w))));
        }
        for (; k < cnt; k++) edge_fma(acc, tab, lane, cw, k);
        cw = cw_next;
    }
    // self loop: dinv^2 * own row
    float  di = g_dinv[gw];
    uint2  u  = tab[(size_t)gw * 32 + lane];
    float2 a  = __half22float2(*(const __half2*)&u.x);
    float2 b  = __half22float2(*(const __half2*)&u.y);
    float  sl = di * di;
    acc.x = di * acc.x + sl * a.x;
    acc.y = di * acc.y + sl * a.y;
    acc.z = di * acc.z + sl * b.x;
    acc.w = di * acc.w + sl * b.y;
    return acc;
}

// -------- 6) hop 1 (x_fp16 -> h1_fp16) --------
__global__ void __launch_bounds__(256) hop1_k(int N) {
    int gw   = (blockIdx.x * blockDim.x + threadIdx.x) >> 5;
    int lane = threadIdx.x & 31;
    if (gw >= N) return;
    float4 acc = hop_row(g_xh, gw, lane);
    uint2 o;
    *(__half2*)&o.x = __floats2half2_rn(acc.x, acc.y);
    *(__half2*)&o.y = __floats2half2_rn(acc.z, acc.w);
    g_h1h[(size_t)gw * 32 + lane] = o;
}

// -------- 7) hop 2 fused with linear projection (W via L1, no smem) --------
__global__ void __launch_bounds__(256) hop2_gemm_k(const float4* __restrict__ W4,
                                                   const float* __restrict__ b,
                                                   float* __restrict__ out,
                                                   int N, int C) {
    int gw   = (blockIdx.x * blockDim.x + threadIdx.x) >> 5;
    int lane = threadIdx.x & 31;
    if (gw >= N) return;

    float4 acc = hop_row(g_h1h, gw, lane);      // h2 row segment [lane*4 .. lane*4+3]

    float my0 = 0.f, my1 = 0.f;
    for (int c = 0; c < C; c++) {
        float4 wv = __ldg(&W4[c * 32 + lane]);  // L1-resident after first block on SM
        float p = acc.x * wv.x + acc.y * wv.y + acc.z * wv.z + acc.w * wv.w;
        p += __shfl_xor_sync(0xffffffffu, p, 16);
        p += __shfl_xor_sync(0xffffffffu, p, 8);
        p += __shfl_xor_sync(0xffffffffu, p, 4);
        p += __shfl_xor_sync(0xffffffffu, p, 2);
        p += __shfl_xor_sync(0xffffffffu, p, 1);
        p += __ldg(&b[c]);
        if (c < 32) { if (lane == c)      my0 = p; }
        else        { if (lane == c - 32) my1 = p; }
    }
    float* orow = out + (size_t)gw * C;
    orow[lane] = my0;
    if (lane < C - 32) orow[32 + lane] = my1;
}

extern "C" void kernel_launch(void* const* d_in, const int* in_sizes, int n_in,
                              void* d_out, int out_size) {
    const float* x  = (const float*)d_in[0];
    const void*  ei = d_in[1];
    const float* W  = (const float*)d_in[2];
    const float* b  = (const float*)d_in[3];

    int C   = in_sizes[3];                 // 40
    int F   = in_sizes[2] / C;             // 128
    int N   = in_sizes[0] / F;             // 100000
    int E   = in_sizes[1] / 2;             // 1600000
    int NB  = (N + 1023) / 1024;
    int NF2 = N * F / 2;

    prep_k<<<1184, 256>>>((const float2*)x, ei, N, NF2);
    hist_k<<<(E + 255) / 256, 256>>>(ei, E);
    scan1_k<<<NB, 256>>>(N);
    scan3_k<<<NB, 1024>>>(N);
    scatter_k<<<(E + 255) / 256, 256>>>(ei, E);

    int blocks = (N * 32 + 255) / 256;     // warp per node
    hop1_k<<<blocks, 256>>>(N);
    hop2_gemm_k<<<blocks, 256>>>((const float4*)W, b, (float*)d_out, N, C);
}

// round 9
// speedup vs baseline: 1.0352x; 1.0352x over previous
#include <cuda_runtime.h>
#include <cuda_fp16.h>

#define N_CAP 100000
#define E_CAP 1600000
#define F_DIM 128

// -------- static scratch (allocation-free rule) --------
__device__ uint2 g_xh [(size_t)N_CAP * 32];   // x  rows in fp16 (25.6 MB)
__device__ uint2 g_h1h[(size_t)N_CAP * 32];   // h1 rows in fp16 (25.6 MB)
__device__ float g_dinv[N_CAP];
__device__ int   g_rowptr[N_CAP + 1];
__device__ int   g_cnt[N_CAP];                // histogram -> cursor
__device__ int2  g_cw[E_CAP];                 // (src, bitcast(dinv[src])) sorted by dst
__device__ int   g_bsums[1024];
__device__ int   g_is64;

// -------- 1) prep: zero histogram + parallel dtype detect + x -> fp16 --------
__global__ void prep_k(const float2* __restrict__ x, const void* ei, int N, int NF2) {
    if (blockIdx.x == 0 && threadIdx.x < 32) {
        const long long* el = (const long long*)ei;
        int ok = 1;
        #pragma unroll
        for (int i = threadIdx.x; i < 128; i += 32) {
            long long v = el[i];
            if (v < 0 || v >= (1LL << 31)) ok = 0;
        }
        ok = __all_sync(0xffffffffu, ok);
        if (threadIdx.x == 0) g_is64 = ok;
    }
    int idx    = blockIdx.x * blockDim.x + threadIdx.x;
    int stride = gridDim.x * blockDim.x;
    for (int i = idx; i < N; i += stride) g_cnt[i] = 0;
    for (int i = idx; i < NF2; i += stride) {
        float2 v = x[i];
        ((__half2*)g_xh)[i] = __floats2half2_rn(v.x, v.y);
    }
}

// -------- 2) histogram of dst --------
__global__ void hist_k(const void* ei, int E) {
    int e = blockIdx.x * blockDim.x + threadIdx.x;
    if (e >= E) return;
    int dst;
    if (g_is64) dst = (int)((const long long*)ei)[(size_t)E + e];
    else        dst = ((const int*)ei)[(size_t)E + e];
    atomicAdd(&g_cnt[dst], 1);
}

// -------- 3) per-1024-chunk totals --------
__global__ void scan1_k(int N) {
    __shared__ int sh[256];
    int base = blockIdx.x * 1024;
    int tid  = threadIdx.x;
    int s = 0;
    #pragma unroll
    for (int k = 0; k < 4; k++) {
        int i = base + tid + k * 256;
        if (i < N) s += g_cnt[i];
    }
    sh[tid] = s; __syncthreads();
    for (int off = 128; off > 0; off >>= 1) {
        if (tid < off) sh[tid] += sh[tid + off];
        __syncthreads();
    }
    if (tid == 0) g_bsums[blockIdx.x] = sh[0];
}

// -------- 4) fused: block prefix + local scan + rowptr + cursor + dinv --------
__global__ void scan3_k(int N) {
    __shared__ int sh[1024];
    __shared__ int bpref;
    int tid = threadIdx.x, bid = blockIdx.x;
    if (tid < 32) {
        int s = 0;
        for (int b = tid; b < bid; b += 32) s += g_bsums[b];
        #pragma unroll
        for (int o = 16; o > 0; o >>= 1) s += __shfl_xor_sync(0xffffffffu, s, o);
        if (tid == 0) bpref = s;
    }
    int i   = bid * 1024 + tid;
    int own = (i < N) ? g_cnt[i] : 0;
    sh[tid] = own; __syncthreads();
    for (int off = 1; off < 1024; off <<= 1) {
        int v = (tid >= off) ? sh[tid - off] : 0;
        __syncthreads();
        sh[tid] += v;
        __syncthreads();
    }
    if (i < N) {
        int excl = bpref + sh[tid] - own;
        g_rowptr[i] = excl;
        g_cnt[i]    = excl;                       // scatter cursor
        g_dinv[i]   = rsqrtf((float)own + 1.0f);
        if (i == N - 1) g_rowptr[N] = excl + own;
    }
}

// -------- 5) scatter edges into CSR with precomputed source weight --------
__global__ void scatter_k(const void* ei, int E) {
    int e = blockIdx.x * blockDim.x + threadIdx.x;
    if (e >= E) return;
    int src, dst;
    if (g_is64) {
        src = (int)((const long long*)ei)[e];
        dst = (int)((const long long*)ei)[(size_t)E + e];
    } else {
        src = ((const int*)ei)[e];
        dst = ((const int*)ei)[(size_t)E + e];
    }
    int pos = atomicAdd(&g_cnt[dst], 1);
    g_cw[pos] = make_int2(src, __float_as_int(g_dinv[src]));
}

// -------- gather core: warp-uniform edge loads (no SHFL), fp16 rows, fp32 acc --------
__device__ __forceinline__ float4 hop_row(const uint2* __restrict__ tab,
                                          int gw, int lane) {
    int beg = g_rowptr[gw], end = g_rowptr[gw + 1];
    float4 acc = make_float4(0.f, 0.f, 0.f, 0.f);
    int j = beg;
    // unroll 4: all lanes load the same edge entries (broadcast, L1-hit after
    // first touch of each 128B line), 4 independent row gathers in flight
    for (; j + 3 < end; j += 4) {
        int2 c0 = g_cw[j];
        int2 c1 = g_cw[j + 1];
        int2 c2 = g_cw[j + 2];
        int2 c3 = g_cw[j + 3];
        uint2 u0 = tab[(size_t)c0.x * 32 + lane];
        uint2 u1 = tab[(size_t)c1.x * 32 + lane];
        uint2 u2 = tab[(size_t)c2.x * 32 + lane];
        uint2 u3 = tab[(size_t)c3.x * 32 + lane];
        float w0 = __int_as_float(c0.y), w1 = __int_as_float(c1.y);
        float w2 = __int_as_float(c2.y), w3 = __int_as_float(c3.y);
        float2 a0 = __half22float2(*(const __half2*)&u0.x);
        float2 b0 = __half22float2(*(const __half2*)&u0.y);
        float2 a1 = __half22float2(*(const __half2*)&u1.x);
        float2 b1 = __half22float2(*(const __half2*)&u1.y);
        float2 a2 = __half22float2(*(const __half2*)&u2.x);
        float2 b2 = __half22float2(*(const __half2*)&u2.y);
        float2 a3 = __half22float2(*(const __half2*)&u3.x);
        float2 b3 = __half22float2(*(const __half2*)&u3.y);
        acc.x = fmaf(w0, a0.x, fmaf(w1, a1.x, fmaf(w2, a2.x, fmaf(w3, a3.x, acc.x))));
        acc.y = fmaf(w0, a0.y, fmaf(w1, a1.y, fmaf(w2, a2.y, fmaf(w3, a3.y, acc.y))));
        acc.z = fmaf(w0, b0.x, fmaf(w1, b1.x, fmaf(w2, b2.x, fmaf(w3, b3.x, acc.z))));
        acc.w = fmaf(w0, b0.y, fmaf(w1, b1.y, fmaf(w2, b2.y, fmaf(w3, b3.y, acc.w))));
    }
    for (; j < end; j++) {
        int2  c = g_cw[j];
        float w = __int_as_float(c.y);
        uint2 u = tab[(size_t)c.x * 32 + lane];
        float2 a = __half22float2(*(const __half2*)&u.x);
        float2 b = __half22float2(*(const __half2*)&u.y);
        acc.x = fmaf(w, a.x, acc.x);
        acc.y = fmaf(w, a.y, acc.y);
        acc.z = fmaf(w, b.x, acc.z);
        acc.w = fmaf(w, b.y, acc.w);
    }
    // self loop: dinv^2 * own row
    float  di = g_dinv[gw];
    uint2  u  = tab[(size_t)gw * 32 + lane];
    float2 a  = __half22float2(*(const __half2*)&u.x);
    float2 b  = __half22float2(*(const __half2*)&u.y);
    float  sl = di * di;
    acc.x = di * acc.x + sl * a.x;
    acc.y = di * acc.y + sl * a.y;
    acc.z = di * acc.z + sl * b.x;
    acc.w = di * acc.w + sl * b.y;
    return acc;
}

// -------- 6) hop 1 (x_fp16 -> h1_fp16) --------
__global__ void __launch_bounds__(256) hop1_k(int N) {
    int gw   = (blockIdx.x * blockDim.x + threadIdx.x) >> 5;
    int lane = threadIdx.x & 31;
    if (gw >= N) return;
    float4 acc = hop_row(g_xh, gw, lane);
    uint2 o;
    *(__half2*)&o.x = __floats2half2_rn(acc.x, acc.y);
    *(__half2*)&o.y = __floats2half2_rn(acc.z, acc.w);
    g_h1h[(size_t)gw * 32 + lane] = o;
}

// -------- 7) hop 2 fused with linear projection (smem W, R6-proven) --------
__global__ void __launch_bounds__(256) hop2_gemm_k(const float* __restrict__ W,
                                                   const float* __restrict__ b,
                                                   float* __restrict__ out,
                                                   int N, int C) {
    extern __shared__ float sm[];               // C*F + C floats
    const float4* sW4 = (const float4*)sm;
    float*        sb  = sm + C * F_DIM;
    for (int idx = threadIdx.x; idx < C * F_DIM; idx += blockDim.x) sm[idx] = W[idx];
    for (int idx = threadIdx.x; idx < C; idx += blockDim.x) sb[idx] = b[idx];
    __syncthreads();

    int gw   = (blockIdx.x * blockDim.x + threadIdx.x) >> 5;
    int lane = threadIdx.x & 31;
    if (gw >= N) return;

    float4 acc = hop_row(g_h1h, gw, lane);      // h2 row segment [lane*4 .. lane*4+3]

    float my0 = 0.f, my1 = 0.f;
    for (int c = 0; c < C; c++) {
        float4 wv = sW4[c * 32 + lane];
        float p = acc.x * wv.x + acc.y * wv.y + acc.z * wv.z + acc.w * wv.w;
        p += __shfl_xor_sync(0xffffffffu, p, 16);
        p += __shfl_xor_sync(0xffffffffu, p, 8);
        p += __shfl_xor_sync(0xffffffffu, p, 4);
        p += __shfl_xor_sync(0xffffffffu, p, 2);
        p += __shfl_xor_sync(0xffffffffu, p, 1);
        p += sb[c];
        if (c < 32) { if (lane == c)      my0 = p; }
        else        { if (lane == c - 32) my1 = p; }
    }
    float* orow = out + (size_t)gw * C;
    orow[lane] = my0;
    if (lane < C - 32) orow[32 + lane] = my1;
}

extern "C" void kernel_launch(void* const* d_in, const int* in_sizes, int n_in,
                              void* d_out, int out_size) {
    const float* x  = (const float*)d_in[0];
    const void*  ei = d_in[1];
    const float* W  = (const float*)d_in[2];
    const float* b  = (const float*)d_in[3];

    int C   = in_sizes[3];                 // 40
    int F   = in_sizes[2] / C;             // 128
    int N   = in_sizes[0] / F;             // 100000
    int E   = in_sizes[1] / 2;             // 1600000
    int NB  = (N + 1023) / 1024;
    int NF2 = N * F / 2;

    prep_k<<<1184, 256>>>((const float2*)x, ei, N, NF2);
    hist_k<<<(E + 255) / 256, 256>>>(ei, E);
    scan1_k<<<NB, 256>>>(N);
    scan3_k<<<NB, 1024>>>(N);
    scatter_k<<<(E + 255) / 256, 256>>>(ei, E);

    int blocks = (N * 32 + 255) / 256;     // warp per node
    hop1_k<<<blocks, 256>>>(N);
    size_t shmem = (size_t)(C * F_DIM + C) * sizeof(float);
    hop2_gemm_k<<<blocks, 256, shmem>>>(W, b, (float*)d_out, N, C);
}